// round 14
// baseline (speedup 1.0000x reference)
#include <cuda_runtime.h>
#include <cuda_fp16.h>

// LieTransport bilinear backward warp — tap-tile binned gather (LTS-byte cut).
// h_prev: [B=4, C=64, H=128, W=128, R=16] fp32 (64B per (b,c,y,x) vector)
//
// Binder identified: L2 (LTS) bytes. 1GB tap reads never hit L1 because the
// ~4 readers of each input line are scattered output pixels on different SMs.
// Fix: bin output pixels by 8x8 input tile of their top-left tap; a gather
// block = (tile, 4 channels) has a ~25KB tap working set -> L1-resident, so
// repeated lines are L1 hits and L2 read traffic drops ~2.5x.
// Prepass: ONE binning kernel into capacity-slotted bins (atomic rank,
// CAP=192 >> mean 64), overflow list for correctness. No scan, no re-scatter.
// Gather warp iteration: 1 pixel x 4 channels — 128B span loads (both
// x-taps contiguous), per-lane y-blend, fp16 shfl_xor(4) exchange, x-blend,
// 4x64B .cs stores from the h==0 half-warp.

#define Hd 128
#define Wd 128
#define Cd 64
#define HWd (Hd * Wd)
#define NPIX (4 * HWd)
#define NTILE 1024                 // 4 batches x 16x16 tiles
#define CAP 192

__device__ unsigned g_cnt[NTILE];
__device__ unsigned g_ovfn;
__device__ uint4    g_rec[NTILE * CAP];   // 3 MB
__device__ uint4    g_ovf[NPIX];          // overflow (normally empty)

// ---- K0: zero counters ----
__global__ void k_zero()
{
    g_cnt[threadIdx.x] = 0u;
    if (threadIdx.x == 0) g_ovfn = 0u;
}

// ---- K1: bin pixels by tap tile, capacity-slotted ----
__global__ __launch_bounds__(256) void k_bin(
    const float* __restrict__ flow, const float* __restrict__ dt)
{
    const int pid = blockIdx.x * 256 + threadIdx.x;
    const int b = pid >> 14;
    const int y = (pid >> 7) & (Hd - 1);
    const int x = pid & (Wd - 1);

    const float d   = dt[b];
    const float d64 = d * 64.0f;
    const int   fb  = ((b * 2) * Hd + y) * Wd + x;
    const float fx  = flow[fb];
    const float fy  = flow[fb + HWd];

    const float ix = fminf(fmaxf(
        fmaf((float)x, 128.0f / 127.0f, fmaf(-fx, d64, -0.5f)), 0.0f), 127.0f);
    const float iy = fminf(fmaxf(
        fmaf((float)y, 128.0f / 127.0f, fmaf(-fy, d64, -0.5f)), 0.0f), 127.0f);

    const float x0f = floorf(ix);
    const float y0f = floorf(iy);
    const float wx  = ix - x0f;
    const float wy  = iy - y0f;

    const int x0 = (int)x0f;
    const int y0 = (int)y0f;
    const int xs = min(x0, Wd - 2);
    const unsigned edge = (x0 == Wd - 1) ? 1u : 0u;

    const int tile = b * 256 + (y0 >> 3) * 16 + (x0 >> 3);

    uint4 rec;
    rec.x = (unsigned)x | ((unsigned)y << 7) | ((unsigned)xs << 14)
          | ((unsigned)y0 << 21) | (edge << 28);
    rec.y = (unsigned)tile;
    rec.z = __float_as_uint(wx);
    rec.w = __float_as_uint(wy);

    const unsigned rank = atomicAdd(&g_cnt[tile], 1u);
    if (rank < CAP) {
        g_rec[tile * CAP + rank] = rec;
    } else {
        const unsigned o = atomicAdd(&g_ovfn, 1u);
        g_ovf[o] = rec;
    }
}

// ---- warp body: 1 pixel x 4 channels (cg block) ----
__device__ __forceinline__ void warp_task(
    const float4* __restrict__ h4, float4* __restrict__ out4,
    const uint4 rec, int b, int cg, int lane)
{
    const int e = lane & 7;       // position in 128B span
    const int h = e >> 2;         // span half (x-tap 0 or 1)
    const int q = e & 3;          // float4 quarter of R=16
    const int u = lane >> 3;      // channel sub 0..3

    const int  x    = rec.x & 127;
    const int  y    = (rec.x >> 7) & 127;
    const int  xs   = (rec.x >> 14) & 127;
    const int  y0   = (rec.x >> 21) & 127;
    const bool edge = (rec.x >> 28) & 1;
    const float wx  = __uint_as_float(rec.z);
    const float wy  = __uint_as_float(rec.w);
    const int  y1   = min(y0 + 1, Hd - 1);

    const float c0 = edge ? 0.0f : (1.0f - wx);
    const float c1 = edge ? 1.0f : wx;
    const float cw = h ? c1 : c0;            // my half's weight
    const float ow = h ? c0 : c1;            // partner half's weight

    const int plane = (b * Cd + cg * 4 + u) * HWd;

    const float4 t  = __ldg(h4 + (plane + y0 * Wd + xs) * 4 + e);
    const float4 bt = __ldg(h4 + (plane + y1 * Wd + xs) * 4 + e);

    float4 m;
    m.x = fmaf(wy, bt.x - t.x, t.x);
    m.y = fmaf(wy, bt.y - t.y, t.y);
    m.z = fmaf(wy, bt.z - t.z, t.z);
    m.w = fmaf(wy, bt.w - t.w, t.w);

    const __half2 pa = __floats2half2_rn(m.x, m.y);
    const __half2 pb = __floats2half2_rn(m.z, m.w);
    const unsigned ua = __shfl_xor_sync(0xffffffffu, *(const unsigned*)&pa, 4);
    const unsigned ub = __shfl_xor_sync(0xffffffffu, *(const unsigned*)&pb, 4);
    const float2 oa = __half22float2(*(const __half2*)&ua);
    const float2 ob = __half22float2(*(const __half2*)&ub);

    float4 r;
    r.x = fmaf(ow, oa.x, cw * m.x);
    r.y = fmaf(ow, oa.y, cw * m.y);
    r.z = fmaf(ow, ob.x, cw * m.z);
    r.w = fmaf(ow, ob.y, cw * m.w);

    if (h == 0)
        __stcs(out4 + (plane + y * Wd + x) * 4 + q, r);
}

// ---- K2: main binned gather. Block = (tile, 4-channel group). ----
__global__ __launch_bounds__(256) void k_gather(
    const float4* __restrict__ h4, float4* __restrict__ out4)
{
    const int tile = blockIdx.x;
    const int cg   = blockIdx.y;
    const int b    = tile >> 8;
    const unsigned n = min(g_cnt[tile], (unsigned)CAP);

    const int w    = threadIdx.x >> 5;
    const int lane = threadIdx.x & 31;

    if ((unsigned)w >= n) return;

    // software-pipelined record fetch (broadcast LDG.128)
    uint4 rec = g_rec[tile * CAP + w];
    for (unsigned i = w; i < n; i += 8) {
        const unsigned nx = i + 8;
        uint4 next;
        if (nx < n) next = g_rec[tile * CAP + nx];
        warp_task(h4, out4, rec, b, cg, lane);
        rec = next;
    }
}

// ---- K3: overflow cleanup (normally n=0, exits immediately) ----
__global__ __launch_bounds__(256) void k_overflow(
    const float4* __restrict__ h4, float4* __restrict__ out4)
{
    const unsigned n = g_ovfn;
    if (n == 0) return;
    const int w    = (blockIdx.x * 256 + threadIdx.x) >> 5;  // global warp id
    const int lane = threadIdx.x & 31;
    const unsigned ntask = n * 16;                 // pixel x channel-group
    for (unsigned tsk = w; tsk < ntask; tsk += 32 * 8) {
        const uint4 rec = g_ovf[tsk >> 4];
        const int   cg  = tsk & 15;
        const int   b   = (int)(rec.y >> 8);
        warp_task(h4, out4, rec, b, cg, lane);
    }
}

extern "C" void kernel_launch(void* const* d_in, const int* in_sizes, int n_in,
                              void* d_out, int out_size)
{
    const float* h_prev = (const float*)d_in[0];
    const float* flow   = (const float*)d_in[1];
    const float* dt     = (const float*)d_in[2];
    float* out          = (float*)d_out;

    k_zero<<<1, NTILE>>>();
    k_bin<<<NPIX / 256, 256>>>(flow, dt);

    dim3 grid(NTILE, Cd / 4);      // 1024 tiles x 16 channel groups
    k_gather<<<grid, 256>>>((const float4*)h_prev, (float4*)out);
    k_overflow<<<32, 256>>>((const float4*)h_prev, (float4*)out);
}

// round 15
// speedup vs baseline: 1.1792x; 1.1792x over previous
#include <cuda_runtime.h>

// LieTransport bilinear backward warp — binned tiles + SMEM-staged halos.
// h_prev: [B=4, C=64, H=128, W=128, R=16] fp32 (64B per (b,c,y,x) vector)
//
// Binder: L2 bytes (1.25GB at LTS cap ~= 100us for all flat variants).
// Fix: bin output pixels by the 8x8 input tile of their top-left tap
// (CAP=2048 slots; border tiles collect clamped pixels, worst ~900).
// Gather block = (tile, 8 channels): stage the 9x9 halo of the tile for its
// 8 channels into 42.6KB smem (every line fetched from L2 exactly ONCE),
// then each warp samples records from smem in exact fp32.
// Overflow backstop: parallel per-(rec,ch,quarter) kernel (empty normally).

#define Hd 128
#define Wd 128
#define Cd 64
#define HWd (Hd * Wd)
#define NPIX (4 * HWd)
#define NTILE 1024                 // 4 batches x 16x16 tiles
#define CAP 2048

#define ROW_F4 37                  // 9 px * 4 quarters + 1 pad (bank skew)
#define CH_F4  (9 * ROW_F4)        // 333 float4 per channel (9 halo rows)
#define SM_F4  (8 * CH_F4)         // 2664 float4 = 42,624 B

__device__ unsigned g_cnt[NTILE];
__device__ unsigned g_ovfn;
__device__ uint4    g_rec[NTILE * CAP];   // 32 MB static scratch
__device__ uint4    g_ovf[NPIX];

// ---- K0: zero counters ----
__global__ void k_zero()
{
    g_cnt[threadIdx.x] = 0u;
    if (threadIdx.x == 0) g_ovfn = 0u;
}

// ---- K1: bin pixels by tap tile ----
__global__ __launch_bounds__(256) void k_bin(
    const float* __restrict__ flow, const float* __restrict__ dt)
{
    const int pid = blockIdx.x * 256 + threadIdx.x;
    const int b = pid >> 14;
    const int y = (pid >> 7) & (Hd - 1);
    const int x = pid & (Wd - 1);

    // folded coords: ix = clamp(x*(128/127) - fx*(64*d) - 0.5, 0, 127)
    const float d   = dt[b];
    const float d64 = d * 64.0f;
    const int   fb  = ((b * 2) * Hd + y) * Wd + x;
    const float fx  = flow[fb];
    const float fy  = flow[fb + HWd];

    const float ix = fminf(fmaxf(
        fmaf((float)x, 128.0f / 127.0f, fmaf(-fx, d64, -0.5f)), 0.0f), 127.0f);
    const float iy = fminf(fmaxf(
        fmaf((float)y, 128.0f / 127.0f, fmaf(-fy, d64, -0.5f)), 0.0f), 127.0f);

    const float x0f = floorf(ix);
    const float y0f = floorf(iy);

    const int x0 = (int)x0f;
    const int y0 = (int)y0f;
    const int tile = b * 256 + (y0 >> 3) * 16 + (x0 >> 3);

    uint4 rec;
    rec.x = (unsigned)x | ((unsigned)y << 7) | ((unsigned)x0 << 14) | ((unsigned)y0 << 21);
    rec.y = (unsigned)tile;
    rec.z = __float_as_uint(ix - x0f);
    rec.w = __float_as_uint(iy - y0f);

    const unsigned rank = atomicAdd(&g_cnt[tile], 1u);
    if (rank < CAP) {
        g_rec[tile * CAP + rank] = rec;
    } else {
        const unsigned o = atomicAdd(&g_ovfn, 1u);
        g_ovf[o] = rec;
    }
}

// ---- K2: staged gather. Block = (tile, 8-channel group). ----
__global__ __launch_bounds__(256) void k_gather(
    const float4* __restrict__ h4, float4* __restrict__ out4)
{
    __shared__ float4 s[SM_F4];

    const int tile = blockIdx.x;
    const int cg   = blockIdx.y;            // 0..7 -> channels cg*8..cg*8+7
    const int b    = tile >> 8;
    const int ty   = ((tile >> 4) & 15) * 8;
    const int tx   = (tile & 15) * 8;

    const unsigned n = min(g_cnt[tile], (unsigned)CAP);
    if (n == 0) return;

    const int tid = threadIdx.x;
    const int ch0 = cg * 8;

    // ---- stage halo: 8 ch x 9 rows x 9 px x 4 quarters = 2592 float4 ----
    for (int idx = tid; idx < 8 * 9 * 36; idx += 256) {
        const int i    = idx % 36;           // px*4 + q within row
        const int task = idx / 36;
        const int u    = task / 9;           // channel sub 0..7
        const int r    = task % 9;           // halo row
        const int px   = i >> 2;
        const int q    = i & 3;
        const int gy   = min(ty + r,  127);  // clamped dup rows never read
        const int gx   = min(tx + px, 127);
        const int plane = (b * Cd + ch0 + u) * HWd;
        s[u * CH_F4 + r * ROW_F4 + i] = __ldg(h4 + (plane + gy * Wd + gx) * 4 + q);
    }
    __syncthreads();

    // ---- sample records from smem ----
    const int w    = tid >> 5;
    const int lane = tid & 31;
    const int u    = lane >> 2;              // channel sub 0..7
    const int q    = lane & 3;               // float4 quarter
    const int plane = (b * Cd + ch0 + u) * HWd;
    const int sbase = u * CH_F4;

    for (unsigned i = w; i < n; i += 8) {
        const uint4 rec = g_rec[tile * CAP + i];
        const int x  = rec.x & 127;
        const int y  = (rec.x >> 7) & 127;
        const int x0 = (rec.x >> 14) & 127;
        const int y0 = (rec.x >> 21) & 127;
        const float wx = __uint_as_float(rec.z);
        const float wy = __uint_as_float(rec.w);

        const int px0 = x0 - tx;
        const int py0 = y0 - ty;
        const int px1 = min(x0 + 1, 127) - tx;
        const int py1 = min(y0 + 1, 127) - ty;

        const float4 v00 = s[sbase + py0 * ROW_F4 + px0 * 4 + q];
        const float4 v01 = s[sbase + py0 * ROW_F4 + px1 * 4 + q];
        const float4 v10 = s[sbase + py1 * ROW_F4 + px0 * 4 + q];
        const float4 v11 = s[sbase + py1 * ROW_F4 + px1 * 4 + q];

        float4 top, bot, r;
        top.x = fmaf(wx, v01.x - v00.x, v00.x);
        top.y = fmaf(wx, v01.y - v00.y, v00.y);
        top.z = fmaf(wx, v01.z - v00.z, v00.z);
        top.w = fmaf(wx, v01.w - v00.w, v00.w);
        bot.x = fmaf(wx, v11.x - v10.x, v10.x);
        bot.y = fmaf(wx, v11.y - v10.y, v10.y);
        bot.z = fmaf(wx, v11.z - v10.z, v10.z);
        bot.w = fmaf(wx, v11.w - v10.w, v10.w);
        r.x = fmaf(wy, bot.x - top.x, top.x);
        r.y = fmaf(wy, bot.y - top.y, top.y);
        r.z = fmaf(wy, bot.z - top.z, top.z);
        r.w = fmaf(wy, bot.w - top.w, top.w);

        __stcs(out4 + (plane + y * Wd + x) * 4 + q, r);
    }
}

// ---- K3: overflow backstop, thread per (record, channel, quarter) ----
__global__ __launch_bounds__(256) void k_overflow(
    const float4* __restrict__ h4, float4* __restrict__ out4)
{
    const unsigned n = g_ovfn;
    if (n == 0) return;
    const unsigned total  = n * Cd * 4;
    const unsigned stride = gridDim.x * 256;
    for (unsigned idx = blockIdx.x * 256 + threadIdx.x; idx < total; idx += stride) {
        const uint4 rec = g_ovf[idx / (Cd * 4)];
        const int rem = idx & (Cd * 4 - 1);
        const int ch  = rem >> 2;
        const int q   = rem & 3;

        const int b  = (int)(rec.y >> 8);
        const int x  = rec.x & 127;
        const int y  = (rec.x >> 7) & 127;
        const int x0 = (rec.x >> 14) & 127;
        const int y0 = (rec.x >> 21) & 127;
        const float wx = __uint_as_float(rec.z);
        const float wy = __uint_as_float(rec.w);
        const int x1 = min(x0 + 1, 127);
        const int y1 = min(y0 + 1, 127);

        const int plane = (b * Cd + ch) * HWd;
        const float4 v00 = __ldg(h4 + (plane + y0 * Wd + x0) * 4 + q);
        const float4 v01 = __ldg(h4 + (plane + y0 * Wd + x1) * 4 + q);
        const float4 v10 = __ldg(h4 + (plane + y1 * Wd + x0) * 4 + q);
        const float4 v11 = __ldg(h4 + (plane + y1 * Wd + x1) * 4 + q);

        float4 top, bot, r;
        top.x = fmaf(wx, v01.x - v00.x, v00.x);
        top.y = fmaf(wx, v01.y - v00.y, v00.y);
        top.z = fmaf(wx, v01.z - v00.z, v00.z);
        top.w = fmaf(wx, v01.w - v00.w, v00.w);
        bot.x = fmaf(wx, v11.x - v10.x, v10.x);
        bot.y = fmaf(wx, v11.y - v10.y, v10.y);
        bot.z = fmaf(wx, v11.z - v10.z, v10.z);
        bot.w = fmaf(wx, v11.w - v10.w, v10.w);
        r.x = fmaf(wy, bot.x - top.x, top.x);
        r.y = fmaf(wy, bot.y - top.y, top.y);
        r.z = fmaf(wy, bot.z - top.z, top.z);
        r.w = fmaf(wy, bot.w - top.w, top.w);

        out4[(plane + y * Wd + x) * 4 + q] = r;
    }
}

extern "C" void kernel_launch(void* const* d_in, const int* in_sizes, int n_in,
                              void* d_out, int out_size)
{
    const float* h_prev = (const float*)d_in[0];
    const float* flow   = (const float*)d_in[1];
    const float* dt     = (const float*)d_in[2];
    float* out          = (float*)d_out;

    k_zero<<<1, NTILE>>>();
    k_bin<<<NPIX / 256, 256>>>(flow, dt);

    dim3 grid(NTILE, 8);           // 1024 tiles x 8 channel groups
    k_gather<<<grid, 256>>>((const float4*)h_prev, (float4*)out);
    k_overflow<<<128, 256>>>((const float4*)h_prev, (float4*)out);
}